// round 3
// baseline (speedup 1.0000x reference)
#include <cuda_runtime.h>

// convection_vectors: (N_NODES, 3) float32      -> d_in[0]
// mesh_elements:      (E, 4)       int32        -> d_in[1]
// inv_matrices:       (E, 4, 4)    float32      -> d_in[2]
// out:                (E, 4, 3)    float32      -> d_out
//
// out[e,i,c] = sum_j inv[e,i,j] * conv[mesh[e,j], c]

#define MAX_NODES 400000

// Padded gather table: (N, 4) so each vertex is one aligned 16B load. 6.4 MB -> L2-resident.
__device__ float4 g_conv4[MAX_NODES];

// One thread per output WORD of the padded table: fully coalesced stores.
__global__ void __launch_bounds__(256)
pad_conv_kernel(const float* __restrict__ conv, int n_words /* 4*N */)
{
    int j = blockIdx.x * blockDim.x + threadIdx.x;
    if (j >= n_words) return;
    int node = j >> 2;
    int c    = j & 3;
    float v = (c < 3) ? __ldg(conv + (long)node * 3 + c) : 0.0f;
    reinterpret_cast<float*>(g_conv4)[j] = v;
}

// Warp store transpose: lane L holds 3 floats (row t = warp_base + L).
// Warp's 96 output floats are written as 24 coalesced float4 by lanes 0..23.
// Each lane's float4 sources from at most 2 lanes -> 6 SHFLs.
__device__ __forceinline__ void store_rows_f4(float* __restrict__ out_warp_base,
                                              float r0, float r1, float r2, int lane)
{
    int g0 = 4 * lane;
    int s0 = g0 / 3;
    int s1 = (s0 + 1) & 31;
    float a0 = __shfl_sync(0xffffffffu, r0, s0);
    float a1 = __shfl_sync(0xffffffffu, r1, s0);
    float a2 = __shfl_sync(0xffffffffu, r2, s0);
    float b0 = __shfl_sync(0xffffffffu, r0, s1);
    float b1 = __shfl_sync(0xffffffffu, r1, s1);
    float b2 = __shfl_sync(0xffffffffu, r2, s1);

    float v[4];
#pragma unroll
    for (int m = 0; m < 4; m++) {
        int g = g0 + m;
        int s = g / 3;
        int c = g - 3 * s;
        float fa = (c == 0) ? a0 : ((c == 1) ? a1 : a2);
        float fb = (c == 0) ? b0 : ((c == 1) ? b1 : b2);
        v[m] = (s == s0) ? fa : fb;
    }
    if (lane < 24)
        reinterpret_cast<float4*>(out_warp_base)[lane] = make_float4(v[0], v[1], v[2], v[3]);
}

// One thread per TWO (element,row) units: rows t and t+half (both warp-coalesced).
__global__ void __launch_bounds__(256)
fem_row_kernel(const int4*   __restrict__ elems,
               const float4* __restrict__ inv,
               float*        __restrict__ out,
               int half_rows)   // 2*E
{
    int t0 = blockIdx.x * blockDim.x + threadIdx.x;
    if (t0 >= half_rows) return;
    int t1 = t0 + half_rows;
    int lane = threadIdx.x & 31;

    // Independent front-loaded chains for both units (MLP).
    int4 iA = __ldg(&elems[t0 >> 2]);
    int4 iB = __ldg(&elems[t1 >> 2]);
    float4 mA = __ldg(&inv[t0]);
    float4 mB = __ldg(&inv[t1]);

    float4 a0 = g_conv4[iA.x];
    float4 a1 = g_conv4[iA.y];
    float4 a2 = g_conv4[iA.z];
    float4 a3 = g_conv4[iA.w];
    float4 c0 = g_conv4[iB.x];
    float4 c1 = g_conv4[iB.y];
    float4 c2 = g_conv4[iB.z];
    float4 c3 = g_conv4[iB.w];

    float rA0 = fmaf(mA.x, a0.x, fmaf(mA.y, a1.x, fmaf(mA.z, a2.x, mA.w * a3.x)));
    float rA1 = fmaf(mA.x, a0.y, fmaf(mA.y, a1.y, fmaf(mA.z, a2.y, mA.w * a3.y)));
    float rA2 = fmaf(mA.x, a0.z, fmaf(mA.y, a1.z, fmaf(mA.z, a2.z, mA.w * a3.z)));

    float rB0 = fmaf(mB.x, c0.x, fmaf(mB.y, c1.x, fmaf(mB.z, c2.x, mB.w * c3.x)));
    float rB1 = fmaf(mB.x, c0.y, fmaf(mB.y, c1.y, fmaf(mB.z, c2.y, mB.w * c3.y)));
    float rB2 = fmaf(mB.x, c0.z, fmaf(mB.y, c1.z, fmaf(mB.z, c2.z, mB.w * c3.z)));

    int wbase0 = t0 & ~31;
    int wbase1 = t1 & ~31;
    bool warp_full = (wbase0 + 32 <= half_rows);   // warp-uniform

    if (warp_full) {
        store_rows_f4(out + (long)wbase0 * 3, rA0, rA1, rA2, lane);
        store_rows_f4(out + (long)wbase1 * 3, rB0, rB1, rB2, lane);
    } else {
        float* o0 = out + (long)t0 * 3;
        o0[0] = rA0; o0[1] = rA1; o0[2] = rA2;
        float* o1 = out + (long)t1 * 3;
        o1[0] = rB0; o1[1] = rB1; o1[2] = rB2;
    }
}

extern "C" void kernel_launch(void* const* d_in, const int* in_sizes, int n_in,
                              void* d_out, int out_size)
{
    const float* conv  = (const float*)d_in[0];
    const int4*  elems = (const int4*)d_in[1];
    const float4* inv  = (const float4*)d_in[2];
    float* out = (float*)d_out;

    int n_nodes = in_sizes[0] / 3;
    int E = in_sizes[1] / 4;
    int half_rows = 2 * E;          // 2 units per thread over 4*E rows

    int block = 256;
    int n_words = 4 * n_nodes;
    pad_conv_kernel<<<(n_words + block - 1) / block, block>>>(conv, n_words);
    fem_row_kernel<<<(half_rows + block - 1) / block, block>>>(elems, inv, out, half_rows);
}